// round 1
// baseline (speedup 1.0000x reference)
#include <cuda_runtime.h>
#include <math.h>
#include <stdint.h>

#define TMAX      131072
#define NT        128          // timesteps per block
#define K1_THREADS 256
#define FLOOR_Y   (-0.93f)
#define GRAV      (-0.0018f)

// ---------------- scan state: (sum_x, sum_z, a, b) ----------------
// y-recurrence: root' = max(root + vy, FLOOR_Y - fmin) == f(x)=max(x+a,b)
// composition (first L, then R): (La+Ra, max(Lb+Ra, Rb)); x,z are plain sums.
struct SState { float sx, sz, a, b; };

__device__ __forceinline__ SState s_identity() {
    SState s; s.sx = 0.f; s.sz = 0.f; s.a = 0.f; s.b = -INFINITY; return s;
}
__device__ __forceinline__ SState s_combine(SState l, SState r) {
    SState o;
    o.sx = l.sx + r.sx;
    o.sz = l.sz + r.sz;
    o.a  = l.a  + r.a;
    o.b  = fmaxf(l.b + r.a, r.b);
    return o;
}
__device__ __forceinline__ float4 to4(SState s)   { return make_float4(s.sx, s.sz, s.a, s.b); }
__device__ __forceinline__ SState from4(float4 f) { SState s; s.sx=f.x; s.sz=f.y; s.a=f.z; s.b=f.w; return s; }

// ---------------- scratch (static device globals; no allocs) ----------------
__device__ float4 g_scratch[TMAX];
__device__ float4 g_blockAgg[TMAX / NT];
__device__ float4 g_blockIncl[TMAX / NT];

// ---------------- FK ----------------
__device__ __forceinline__ void mat_mul3(const float* A, const float* B, float* C) {
#pragma unroll
    for (int r = 0; r < 3; r++)
#pragma unroll
        for (int c = 0; c < 3; c++)
            C[r*3+c] = A[r*3+0]*B[0*3+c] + A[r*3+1]*B[1*3+c] + A[r*3+2]*B[2*3+c];
}
__device__ __forceinline__ void mat_vec_add3(const float* A, const float* v,
                                             const float* pin, float* pout) {
#pragma unroll
    for (int r = 0; r < 3; r++)
        pout[r] = pin[r] + A[r*3+0]*v[0] + A[r*3+1]*v[1] + A[r*3+2]*v[2];
}

// Lower-body slot -> pose joint float offsets (joint*9):
//   slot0->j0 (+0), slot1->j1 (+9), slot2->j2 (+18), slot3->j4 (+36),
//   slot4->j5 (+45), slot5->j7 (+63), slot6->j8 (+72). Slots 7,8 matrices unused.
// feet order FEET=[7,5,8,6]; fmin over slots 5..8 y.
__device__ void fk_feet(const float* __restrict__ m, const float* __restrict__ b,
                        float* feet, float& fmin)
{
    float Rg0[9], R1[9], R2[9];
    float p0[3], pt[3];
#pragma unroll
    for (int i = 0; i < 9; i++) Rg0[i] = m[i];
#pragma unroll
    for (int i = 0; i < 3; i++) p0[i] = b[i];

    float p5_[3], p6_[3], p7_[3], p8_[3];

    // chain A: 0 -> 1 -> 3 -> 5 -> 7
    mat_vec_add3(Rg0, b + 3, p0, pt);          // p1
    mat_mul3(Rg0, m + 9, R1);                  // Rg1
    float p3_[3];
    mat_vec_add3(R1, b + 9, pt, p3_);          // p3
    mat_mul3(R1, m + 36, R2);                  // Rg3
    mat_vec_add3(R2, b + 15, p3_, p5_);        // p5
    mat_mul3(R2, m + 63, R1);                  // Rg5
    mat_vec_add3(R1, b + 21, p5_, p7_);        // p7

    // chain B: 0 -> 2 -> 4 -> 6 -> 8
    mat_vec_add3(Rg0, b + 6, p0, pt);          // p2
    mat_mul3(Rg0, m + 18, R1);                 // Rg2
    float p4_[3];
    mat_vec_add3(R1, b + 12, pt, p4_);         // p4
    mat_mul3(R1, m + 45, R2);                  // Rg4
    mat_vec_add3(R2, b + 18, p4_, p6_);        // p6
    mat_mul3(R2, m + 72, R1);                  // Rg6
    mat_vec_add3(R1, b + 24, p6_, p8_);        // p8

    feet[0] = p7_[0]; feet[1]  = p7_[1]; feet[2]  = p7_[2];
    feet[3] = p5_[0]; feet[4]  = p5_[1]; feet[5]  = p5_[2];
    feet[6] = p8_[0]; feet[7]  = p8_[1]; feet[8]  = p8_[2];
    feet[9] = p6_[0]; feet[10] = p6_[1]; feet[11] = p6_[2];
    fmin = fminf(fminf(p5_[1], p6_[1]), fminf(p7_[1], p8_[1]));
}

// ---------------- K1: copy pose slab + FK + velocity + block scan ----------------
__global__ void __launch_bounds__(K1_THREADS)
k1_fused(const float* __restrict__ pose, const float* __restrict__ bone,
         const int* __restrict__ index, float* __restrict__ out, int T)
{
    __shared__ float  s_bone[27];
    __shared__ float  s_feet[(NT + 1) * 12];
    __shared__ float4 s_warp[K1_THREADS / 32];

    const int tid = threadIdx.x;
    const int t0  = blockIdx.x * NT;
    if (tid < 27) s_bone[tid] = bone[tid];

    // --- copy this block's pose slab to d_out (coalesced float4), warming L1/L2 ---
    {
        const float4* src = (const float4*)pose;
        float4*       dst = (float4*)out;
        const size_t base4 = (size_t)t0 * 54;       // 216 floats = 54 float4 per t
        const size_t tot4  = (size_t)T * 54;
#pragma unroll 4
        for (int i = tid; i < NT * 54; i += K1_THREADS) {
            size_t g = base4 + (size_t)i;
            if (g < tot4) dst[g] = src[g];
        }
    }
    __syncthreads();   // s_bone ready; slab resident in cache

    // --- FK for my timestep (threads [0,NT)) ---
    const int  l      = tid;
    float      feetCur[12];
    float      fmin   = 0.f;
    const bool active = (l < NT) && (t0 + l < T);
    if (active) {
        fk_feet(pose + (size_t)(t0 + l) * 216, s_bone, feetCur, fmin);
#pragma unroll
        for (int k = 0; k < 12; k++) s_feet[(l + 1) * 12 + k] = feetCur[k];
    }
    // cross-block boundary: feet at t0-1 (redundant FK, once per block)
    if (tid == 0 && t0 > 0) {
        float fp[12]; float fd;
        fk_feet(pose + (size_t)(t0 - 1) * 216, s_bone, fp, fd);
#pragma unroll
        for (int k = 0; k < 12; k++) s_feet[k] = fp[k];
    }
    __syncthreads();

    // --- per-element scan state ---
    SState v = s_identity();
    if (active) {
        const int t = t0 + l;
        float vx = 0.f, vy = GRAV, vz = 0.f;
        if (t > 0) {
            const int idx = index[t] & 3;
            vx =        s_feet[l*12 + idx*3 + 0] - feetCur[idx*3 + 0];
            vy = GRAV + (s_feet[l*12 + idx*3 + 1] - feetCur[idx*3 + 1]);
            vz =        s_feet[l*12 + idx*3 + 2] - feetCur[idx*3 + 2];
        }
        v.sx = vx; v.sz = vz; v.a = vy; v.b = FLOOR_Y - fmin;
    }

    // --- block-wide inclusive scan (8 warps) ---
    const int lane = tid & 31, warp = tid >> 5;
#pragma unroll
    for (int d = 1; d < 32; d <<= 1) {
        float osx = __shfl_up_sync(0xFFFFFFFFu, v.sx, d);
        float osz = __shfl_up_sync(0xFFFFFFFFu, v.sz, d);
        float oa  = __shfl_up_sync(0xFFFFFFFFu, v.a,  d);
        float ob  = __shfl_up_sync(0xFFFFFFFFu, v.b,  d);
        if (lane >= d) {
            SState o; o.sx = osx; o.sz = osz; o.a = oa; o.b = ob;
            v = s_combine(o, v);
        }
    }
    if (lane == 31) s_warp[warp] = to4(v);
    __syncthreads();
    if (warp == 0) {
        SState w = s_identity();
        if (lane < K1_THREADS / 32) w = from4(s_warp[lane]);
#pragma unroll
        for (int d = 1; d < K1_THREADS / 32; d <<= 1) {
            float osx = __shfl_up_sync(0xFFFFFFFFu, w.sx, d);
            float osz = __shfl_up_sync(0xFFFFFFFFu, w.sz, d);
            float oa  = __shfl_up_sync(0xFFFFFFFFu, w.a,  d);
            float ob  = __shfl_up_sync(0xFFFFFFFFu, w.b,  d);
            if (lane >= d) {
                SState o; o.sx = osx; o.sz = osz; o.a = oa; o.b = ob;
                w = s_combine(o, w);
            }
        }
        if (lane < K1_THREADS / 32) s_warp[lane] = to4(w);
    }
    __syncthreads();
    if (warp > 0) v = s_combine(from4(s_warp[warp - 1]), v);

    if (active) g_scratch[t0 + l] = to4(v);
    if (tid == K1_THREADS - 1) g_blockAgg[blockIdx.x] = to4(v);
}

// ---------------- K2: scan block aggregates (single block) ----------------
__global__ void __launch_bounds__(1024) k2_scan(int nb)
{
    __shared__ float4 s_warp[32];
    const int tid = threadIdx.x, lane = tid & 31, warp = tid >> 5;
    SState v = s_identity();
    if (tid < nb) v = from4(g_blockAgg[tid]);
#pragma unroll
    for (int d = 1; d < 32; d <<= 1) {
        float osx = __shfl_up_sync(0xFFFFFFFFu, v.sx, d);
        float osz = __shfl_up_sync(0xFFFFFFFFu, v.sz, d);
        float oa  = __shfl_up_sync(0xFFFFFFFFu, v.a,  d);
        float ob  = __shfl_up_sync(0xFFFFFFFFu, v.b,  d);
        if (lane >= d) {
            SState o; o.sx = osx; o.sz = osz; o.a = oa; o.b = ob;
            v = s_combine(o, v);
        }
    }
    if (lane == 31) s_warp[warp] = to4(v);
    __syncthreads();
    if (warp == 0) {
        SState w = from4(s_warp[lane]);   // 32 warps exactly
#pragma unroll
        for (int d = 1; d < 32; d <<= 1) {
            float osx = __shfl_up_sync(0xFFFFFFFFu, w.sx, d);
            float osz = __shfl_up_sync(0xFFFFFFFFu, w.sz, d);
            float oa  = __shfl_up_sync(0xFFFFFFFFu, w.a,  d);
            float ob  = __shfl_up_sync(0xFFFFFFFFu, w.b,  d);
            if (lane >= d) {
                SState o; o.sx = osx; o.sz = osz; o.a = oa; o.b = ob;
                w = s_combine(o, w);
            }
        }
        s_warp[lane] = to4(w);
    }
    __syncthreads();
    if (warp > 0) v = s_combine(from4(s_warp[warp - 1]), v);
    if (tid < nb) g_blockIncl[tid] = to4(v);
}

// ---------------- K3: apply block prefixes, emit trans ----------------
__global__ void k3_apply(float* __restrict__ out_trans, int T)
{
    const int t = blockIdx.x * blockDim.x + threadIdx.x;
    if (t >= T) return;
    SState r = from4(g_scratch[t]);
    const int b = t / NT;
    if (b > 0) r = s_combine(from4(g_blockIncl[b - 1]), r);
    out_trans[t*3 + 0] = r.sx;
    out_trans[t*3 + 1] = fmaxf(r.a, r.b);   // root_y[t] = trans_y[t]
    out_trans[t*3 + 2] = r.sz;
}

extern "C" void kernel_launch(void* const* d_in, const int* in_sizes, int n_in,
                              void* d_out, int out_size)
{
    const float* pose  = (const float*)d_in[0];   // (T,24,3,3) f32
    const float* bone  = (const float*)d_in[1];   // (9,3) f32
    const int*   index = (const int*)d_in[2];     // (T,) i32
    float*       out   = (float*)d_out;           // [pose | trans]

    const int T  = in_sizes[2];
    const int nb = (T + NT - 1) / NT;

    k1_fused<<<nb, K1_THREADS>>>(pose, bone, index, out, T);
    k2_scan<<<1, 1024>>>(nb);
    k3_apply<<<(T + 255) / 256, 256>>>(out + (size_t)T * 216, T);
}

// round 2
// speedup vs baseline: 1.0973x; 1.0973x over previous
#include <cuda_runtime.h>
#include <math.h>
#include <stdint.h>

#define TMAX       131072
#define NT         256          // timesteps per block == blockDim
#define K1_THREADS 256
#define NB_MAX     (TMAX / NT)
#define FLOOR_Y    (-0.93f)
#define GRAV       (-0.0018f)

// ---------------- scan state: (sum_x, sum_z, a, b) ----------------
// y-recurrence: root' = max(root + vy, FLOOR_Y - fmin) == f(x)=max(x+a,b)
// composition (first L, then R): (La+Ra, max(Lb+Ra, Rb)); x,z are plain sums.
struct SState { float sx, sz, a, b; };

__device__ __forceinline__ SState s_identity() {
    SState s; s.sx = 0.f; s.sz = 0.f; s.a = 0.f; s.b = -INFINITY; return s;
}
__device__ __forceinline__ SState s_combine(SState l, SState r) {
    SState o;
    o.sx = l.sx + r.sx;
    o.sz = l.sz + r.sz;
    o.a  = l.a  + r.a;
    o.b  = fmaxf(l.b + r.a, r.b);
    return o;
}
__device__ __forceinline__ float4 to4(SState s)   { return make_float4(s.sx, s.sz, s.a, s.b); }
__device__ __forceinline__ SState from4(float4 f) { SState s; s.sx=f.x; s.sz=f.y; s.a=f.z; s.b=f.w; return s; }

// ---------------- scratch (static device globals; no allocs) ----------------
__device__ float4 g_scratch[TMAX];
__device__ float4 g_blockAgg[NB_MAX];
__device__ float4 g_blockIncl[NB_MAX];

// ---------------- FK ----------------
__device__ __forceinline__ void mat_mul3(const float* A, const float* B, float* C) {
#pragma unroll
    for (int r = 0; r < 3; r++)
#pragma unroll
        for (int c = 0; c < 3; c++)
            C[r*3+c] = A[r*3+0]*B[0*3+c] + A[r*3+1]*B[1*3+c] + A[r*3+2]*B[2*3+c];
}
__device__ __forceinline__ void mat_vec_add3(const float* A, const float* v,
                                             const float* pin, float* pout) {
#pragma unroll
    for (int r = 0; r < 3; r++)
        pout[r] = pin[r] + A[r*3+0]*v[0] + A[r*3+1]*v[1] + A[r*3+2]*v[2];
}

// Lower-body slot -> pose joint float offsets (joint*9):
//   slot0->j0 (+0), slot1->j1 (+9), slot2->j2 (+18), slot3->j4 (+36),
//   slot4->j5 (+45), slot5->j7 (+63), slot6->j8 (+72). Slots 7,8 matrices unused.
// feet order FEET=[7,5,8,6]; fmin over slots 5..8 y.
__device__ void fk_feet(const float* __restrict__ m, const float* __restrict__ b,
                        float* feet, float& fmin)
{
    float Rg0[9], R1[9], R2[9];
    float p0[3], pt[3];
#pragma unroll
    for (int i = 0; i < 9; i++) Rg0[i] = m[i];
#pragma unroll
    for (int i = 0; i < 3; i++) p0[i] = b[i];

    float p5_[3], p6_[3], p7_[3], p8_[3];

    // chain A: 0 -> 1 -> 3 -> 5 -> 7
    mat_vec_add3(Rg0, b + 3, p0, pt);          // p1
    mat_mul3(Rg0, m + 9, R1);                  // Rg1
    float p3_[3];
    mat_vec_add3(R1, b + 9, pt, p3_);          // p3
    mat_mul3(R1, m + 36, R2);                  // Rg3
    mat_vec_add3(R2, b + 15, p3_, p5_);        // p5
    mat_mul3(R2, m + 63, R1);                  // Rg5
    mat_vec_add3(R1, b + 21, p5_, p7_);        // p7

    // chain B: 0 -> 2 -> 4 -> 6 -> 8
    mat_vec_add3(Rg0, b + 6, p0, pt);          // p2
    mat_mul3(Rg0, m + 18, R1);                 // Rg2
    float p4_[3];
    mat_vec_add3(R1, b + 12, pt, p4_);         // p4
    mat_mul3(R1, m + 45, R2);                  // Rg4
    mat_vec_add3(R2, b + 18, p4_, p6_);        // p6
    mat_mul3(R2, m + 72, R1);                  // Rg6
    mat_vec_add3(R1, b + 24, p6_, p8_);        // p8

    feet[0] = p7_[0]; feet[1]  = p7_[1]; feet[2]  = p7_[2];
    feet[3] = p5_[0]; feet[4]  = p5_[1]; feet[5]  = p5_[2];
    feet[6] = p8_[0]; feet[7]  = p8_[1]; feet[8]  = p8_[2];
    feet[9] = p6_[0]; feet[10] = p6_[1]; feet[11] = p6_[2];
    fmin = fminf(fminf(p5_[1], p6_[1]), fminf(p7_[1], p8_[1]));
}

// ---------------- K1: copy pose slab + FK + velocity + block scan ----------------
__global__ void __launch_bounds__(K1_THREADS)
k1_fused(const float* __restrict__ pose, const float* __restrict__ bone,
         const int* __restrict__ index, float* __restrict__ out, int T)
{
    __shared__ float  s_bone[27];
    __shared__ float  s_feet[(NT + 1) * 12];
    __shared__ float4 s_warp[K1_THREADS / 32];

    const int tid = threadIdx.x;
    const int t0  = blockIdx.x * NT;
    if (tid < 27) s_bone[tid] = bone[tid];

    // load index early (overlaps with everything)
    const int t_mine  = t0 + tid;
    int idx_mine = 0;
    if (t_mine < T) idx_mine = index[t_mine] & 3;

    // --- copy this block's pose slab to d_out ---
    // 216 floats = 54 float4 per t; NT*54 = 13824 float4 per block, 54/thread.
    // Batched 6-wide loads for MLP; streaming stores (lines never re-read).
    {
        const float4* __restrict__ src = (const float4*)pose;
        float4*       __restrict__ dst = (float4*)out;
        const size_t base4 = (size_t)t0 * 54;
        if (t0 + NT <= T) {
            const float4* s = src + base4;
            float4*       d = dst + base4;
#pragma unroll 1
            for (int it = 0; it < 9; ++it) {
                float4 r0 = s[(it*6 + 0) * K1_THREADS + tid];
                float4 r1 = s[(it*6 + 1) * K1_THREADS + tid];
                float4 r2 = s[(it*6 + 2) * K1_THREADS + tid];
                float4 r3 = s[(it*6 + 3) * K1_THREADS + tid];
                float4 r4 = s[(it*6 + 4) * K1_THREADS + tid];
                float4 r5 = s[(it*6 + 5) * K1_THREADS + tid];
                __stcs(&d[(it*6 + 0) * K1_THREADS + tid], r0);
                __stcs(&d[(it*6 + 1) * K1_THREADS + tid], r1);
                __stcs(&d[(it*6 + 2) * K1_THREADS + tid], r2);
                __stcs(&d[(it*6 + 3) * K1_THREADS + tid], r3);
                __stcs(&d[(it*6 + 4) * K1_THREADS + tid], r4);
                __stcs(&d[(it*6 + 5) * K1_THREADS + tid], r5);
            }
        } else {
            const size_t tot4 = (size_t)T * 54;
            for (int i = tid; i < NT * 54; i += K1_THREADS) {
                size_t g = base4 + (size_t)i;
                if (g < tot4) dst[g] = src[g];
            }
        }
    }
    __syncthreads();   // s_bone ready; slab resident in L1/L2

    // --- FK for my timestep (all threads) ---
    float      feetCur[12];
    float      fmin   = 0.f;
    const bool active = (t_mine < T);
    if (active) {
        fk_feet(pose + (size_t)t_mine * 216, s_bone, feetCur, fmin);
#pragma unroll
        for (int k = 0; k < 12; k++) s_feet[(tid + 1) * 12 + k] = feetCur[k];
    }
    // cross-block boundary: feet at t0-1 (redundant FK, once per block)
    if (tid == 0 && t0 > 0) {
        float fp[12]; float fd;
        fk_feet(pose + (size_t)(t0 - 1) * 216, s_bone, fp, fd);
#pragma unroll
        for (int k = 0; k < 12; k++) s_feet[k] = fp[k];
    }
    __syncthreads();

    // --- per-element scan state ---
    SState v = s_identity();
    if (active) {
        float vx = 0.f, vy = GRAV, vz = 0.f;
        if (t_mine > 0) {
            vx =        s_feet[tid*12 + idx_mine*3 + 0] - feetCur[idx_mine*3 + 0];
            vy = GRAV + (s_feet[tid*12 + idx_mine*3 + 1] - feetCur[idx_mine*3 + 1]);
            vz =        s_feet[tid*12 + idx_mine*3 + 2] - feetCur[idx_mine*3 + 2];
        }
        v.sx = vx; v.sz = vz; v.a = vy; v.b = FLOOR_Y - fmin;
    }

    // --- block-wide inclusive scan (8 warps) ---
    const int lane = tid & 31, warp = tid >> 5;
#pragma unroll
    for (int d = 1; d < 32; d <<= 1) {
        float osx = __shfl_up_sync(0xFFFFFFFFu, v.sx, d);
        float osz = __shfl_up_sync(0xFFFFFFFFu, v.sz, d);
        float oa  = __shfl_up_sync(0xFFFFFFFFu, v.a,  d);
        float ob  = __shfl_up_sync(0xFFFFFFFFu, v.b,  d);
        if (lane >= d) {
            SState o; o.sx = osx; o.sz = osz; o.a = oa; o.b = ob;
            v = s_combine(o, v);
        }
    }
    if (lane == 31) s_warp[warp] = to4(v);
    __syncthreads();
    if (warp == 0) {
        SState w = s_identity();
        if (lane < K1_THREADS / 32) w = from4(s_warp[lane]);
#pragma unroll
        for (int d = 1; d < K1_THREADS / 32; d <<= 1) {
            float osx = __shfl_up_sync(0xFFFFFFFFu, w.sx, d);
            float osz = __shfl_up_sync(0xFFFFFFFFu, w.sz, d);
            float oa  = __shfl_up_sync(0xFFFFFFFFu, w.a,  d);
            float ob  = __shfl_up_sync(0xFFFFFFFFu, w.b,  d);
            if (lane >= d) {
                SState o; o.sx = osx; o.sz = osz; o.a = oa; o.b = ob;
                w = s_combine(o, w);
            }
        }
        if (lane < K1_THREADS / 32) s_warp[lane] = to4(w);
    }
    __syncthreads();
    if (warp > 0) v = s_combine(from4(s_warp[warp - 1]), v);

    if (active) g_scratch[t_mine] = to4(v);
    if (tid == K1_THREADS - 1) g_blockAgg[blockIdx.x] = to4(v);
}

// ---------------- K2: scan block aggregates (single block) ----------------
__global__ void __launch_bounds__(1024) k2_scan(int nb)
{
    __shared__ float4 s_warp[32];
    const int tid = threadIdx.x, lane = tid & 31, warp = tid >> 5;
    SState v = s_identity();
    if (tid < nb) v = from4(g_blockAgg[tid]);
#pragma unroll
    for (int d = 1; d < 32; d <<= 1) {
        float osx = __shfl_up_sync(0xFFFFFFFFu, v.sx, d);
        float osz = __shfl_up_sync(0xFFFFFFFFu, v.sz, d);
        float oa  = __shfl_up_sync(0xFFFFFFFFu, v.a,  d);
        float ob  = __shfl_up_sync(0xFFFFFFFFu, v.b,  d);
        if (lane >= d) {
            SState o; o.sx = osx; o.sz = osz; o.a = oa; o.b = ob;
            v = s_combine(o, v);
        }
    }
    if (lane == 31) s_warp[warp] = to4(v);
    __syncthreads();
    if (warp == 0) {
        SState w = from4(s_warp[lane]);   // 32 warps exactly
#pragma unroll
        for (int d = 1; d < 32; d <<= 1) {
            float osx = __shfl_up_sync(0xFFFFFFFFu, w.sx, d);
            float osz = __shfl_up_sync(0xFFFFFFFFu, w.sz, d);
            float oa  = __shfl_up_sync(0xFFFFFFFFu, w.a,  d);
            float ob  = __shfl_up_sync(0xFFFFFFFFu, w.b,  d);
            if (lane >= d) {
                SState o; o.sx = osx; o.sz = osz; o.a = oa; o.b = ob;
                w = s_combine(o, w);
            }
        }
        s_warp[lane] = to4(w);
    }
    __syncthreads();
    if (warp > 0) v = s_combine(from4(s_warp[warp - 1]), v);
    if (tid < nb) g_blockIncl[tid] = to4(v);
}

// ---------------- K3: apply block prefixes, emit trans ----------------
__global__ void __launch_bounds__(512) k3_apply(float* __restrict__ out_trans, int T)
{
    const int t = blockIdx.x * blockDim.x + threadIdx.x;
    if (t >= T) return;
    SState r = from4(g_scratch[t]);
    const int b = t / NT;
    if (b > 0) r = s_combine(from4(g_blockIncl[b - 1]), r);
    out_trans[t*3 + 0] = r.sx;
    out_trans[t*3 + 1] = fmaxf(r.a, r.b);   // root_y[t] = trans_y[t]
    out_trans[t*3 + 2] = r.sz;
}

extern "C" void kernel_launch(void* const* d_in, const int* in_sizes, int n_in,
                              void* d_out, int out_size)
{
    const float* pose  = (const float*)d_in[0];   // (T,24,3,3) f32
    const float* bone  = (const float*)d_in[1];   // (9,3) f32
    const int*   index = (const int*)d_in[2];     // (T,) i32
    float*       out   = (float*)d_out;           // [pose | trans]

    const int T  = in_sizes[2];
    const int nb = (T + NT - 1) / NT;

    k1_fused<<<nb, K1_THREADS>>>(pose, bone, index, out, T);
    k2_scan<<<1, 1024>>>(nb);
    k3_apply<<<(T + 511) / 512, 512>>>(out + (size_t)T * 216, T);
}

// round 3
// speedup vs baseline: 1.1704x; 1.0667x over previous
#include <cuda_runtime.h>
#include <math.h>
#include <stdint.h>

#define TMAX       131072
#define NT         256          // timesteps per fk block == blockDim
#define THREADS    256
#define NB_MAX     (TMAX / NT)
#define FLOOR_Y    (-0.93f)
#define GRAV       (-0.0018f)

// ---------------- scan state: (sum_x, sum_z, a, b) ----------------
// y-recurrence: root' = max(root + vy, FLOOR_Y - fmin) == f(x)=max(x+a,b)
// composition (first L, then R): (La+Ra, max(Lb+Ra, Rb)); x,z are plain sums.
struct SState { float sx, sz, a, b; };

__device__ __forceinline__ SState s_identity() {
    SState s; s.sx = 0.f; s.sz = 0.f; s.a = 0.f; s.b = -INFINITY; return s;
}
__device__ __forceinline__ SState s_combine(SState l, SState r) {
    SState o;
    o.sx = l.sx + r.sx;
    o.sz = l.sz + r.sz;
    o.a  = l.a  + r.a;
    o.b  = fmaxf(l.b + r.a, r.b);
    return o;
}
__device__ __forceinline__ float4 to4(SState s)   { return make_float4(s.sx, s.sz, s.a, s.b); }
__device__ __forceinline__ SState from4(float4 f) { SState s; s.sx=f.x; s.sz=f.y; s.a=f.z; s.b=f.w; return s; }

// ---------------- scratch (static device globals; no allocs) ----------------
__device__ float4 g_scratch[TMAX];
__device__ float4 g_blockAgg[NB_MAX];
__device__ float4 g_blockIncl[NB_MAX];

// ---------------- FK ----------------
__device__ __forceinline__ void mat_mul3(const float* A, const float* B, float* C) {
#pragma unroll
    for (int r = 0; r < 3; r++)
#pragma unroll
        for (int c = 0; c < 3; c++)
            C[r*3+c] = A[r*3+0]*B[0*3+c] + A[r*3+1]*B[1*3+c] + A[r*3+2]*B[2*3+c];
}
__device__ __forceinline__ void mat_vec_add3(const float* A, const float* v,
                                             const float* pin, float* pout) {
#pragma unroll
    for (int r = 0; r < 3; r++)
        pout[r] = pin[r] + A[r*3+0]*v[0] + A[r*3+1]*v[1] + A[r*3+2]*v[2];
}

// Lower-body slot -> pose joint float offsets (joint*9):
//   slot0->j0 (+0), slot1->j1 (+9), slot2->j2 (+18), slot3->j4 (+36),
//   slot4->j5 (+45), slot5->j7 (+63), slot6->j8 (+72). Slots 7,8 matrices unused.
// feet order FEET=[7,5,8,6]; fmin over slots 5..8 y.
__device__ void fk_feet(const float* __restrict__ m, const float* __restrict__ b,
                        float* feet, float& fmin)
{
    float Rg0[9], R1[9], R2[9];
    float p0[3], pt[3];
#pragma unroll
    for (int i = 0; i < 9; i++) Rg0[i] = m[i];
#pragma unroll
    for (int i = 0; i < 3; i++) p0[i] = b[i];

    float p5_[3], p6_[3], p7_[3], p8_[3];

    // chain A: 0 -> 1 -> 3 -> 5 -> 7
    mat_vec_add3(Rg0, b + 3, p0, pt);          // p1
    mat_mul3(Rg0, m + 9, R1);                  // Rg1
    float p3_[3];
    mat_vec_add3(R1, b + 9, pt, p3_);          // p3
    mat_mul3(R1, m + 36, R2);                  // Rg3
    mat_vec_add3(R2, b + 15, p3_, p5_);        // p5
    mat_mul3(R2, m + 63, R1);                  // Rg5
    mat_vec_add3(R1, b + 21, p5_, p7_);        // p7

    // chain B: 0 -> 2 -> 4 -> 6 -> 8
    mat_vec_add3(Rg0, b + 6, p0, pt);          // p2
    mat_mul3(Rg0, m + 18, R1);                 // Rg2
    float p4_[3];
    mat_vec_add3(R1, b + 12, pt, p4_);         // p4
    mat_mul3(R1, m + 45, R2);                  // Rg4
    mat_vec_add3(R2, b + 18, p4_, p6_);        // p6
    mat_mul3(R2, m + 72, R1);                  // Rg6
    mat_vec_add3(R1, b + 24, p6_, p8_);        // p8

    feet[0] = p7_[0]; feet[1]  = p7_[1]; feet[2]  = p7_[2];
    feet[3] = p5_[0]; feet[4]  = p5_[1]; feet[5]  = p5_[2];
    feet[6] = p8_[0]; feet[7]  = p8_[1]; feet[8]  = p8_[2];
    feet[9] = p6_[0]; feet[10] = p6_[1]; feet[11] = p6_[2];
    fmin = fminf(fminf(p5_[1], p6_[1]), fminf(p7_[1], p8_[1]));
}

// ---------------- K1: interleaved copy blocks + fk/scan blocks ----------------
// bid % 3 == 0  -> fk block (fk_id = bid/3), others -> copy block.
__global__ void __launch_bounds__(THREADS)
k1_mixed(const float* __restrict__ pose, const float* __restrict__ bone,
         const int* __restrict__ index, float* __restrict__ out,
         int T, int nbFK, int nbCopy)
{
    const int tid = threadIdx.x;
    const int bid = blockIdx.x;

    if (bid % 3 != 0) {
        // ================= COPY BLOCK =================
        const int cid = bid - (bid / 3 + 1);
        const size_t tot4  = (size_t)T * 54;                 // float4 count
        const size_t chunk = (tot4 + nbCopy - 1) / nbCopy;
        const size_t beg   = (size_t)cid * chunk;
        const size_t end   = (beg + chunk < tot4) ? beg + chunk : tot4;
        if (beg >= end) return;

        const float4* __restrict__ src = (const float4*)pose;
        float4*       __restrict__ dst = (float4*)out;

        size_t pos = beg;
        // 8-wide batches: full coverage of [pos, pos+2048)
        while (pos + 8 * THREADS <= end) {
            float4 r0 = __ldcs(&src[pos + 0*THREADS + tid]);
            float4 r1 = __ldcs(&src[pos + 1*THREADS + tid]);
            float4 r2 = __ldcs(&src[pos + 2*THREADS + tid]);
            float4 r3 = __ldcs(&src[pos + 3*THREADS + tid]);
            float4 r4 = __ldcs(&src[pos + 4*THREADS + tid]);
            float4 r5 = __ldcs(&src[pos + 5*THREADS + tid]);
            float4 r6 = __ldcs(&src[pos + 6*THREADS + tid]);
            float4 r7 = __ldcs(&src[pos + 7*THREADS + tid]);
            __stcs(&dst[pos + 0*THREADS + tid], r0);
            __stcs(&dst[pos + 1*THREADS + tid], r1);
            __stcs(&dst[pos + 2*THREADS + tid], r2);
            __stcs(&dst[pos + 3*THREADS + tid], r3);
            __stcs(&dst[pos + 4*THREADS + tid], r4);
            __stcs(&dst[pos + 5*THREADS + tid], r5);
            __stcs(&dst[pos + 6*THREADS + tid], r6);
            __stcs(&dst[pos + 7*THREADS + tid], r7);
            pos += 8 * THREADS;
        }
        for (size_t i = pos + tid; i < end; i += THREADS)
            __stcs(&dst[i], __ldcs(&src[i]));
        return;
    }

    // ================= FK / SCAN BLOCK =================
    const int fkid = bid / 3;
    if (fkid >= nbFK) return;

    __shared__ float  s_bone[27];
    __shared__ float  s_feet[(NT + 1) * 12];
    __shared__ float4 s_warp[THREADS / 32];

    const int t0 = fkid * NT;
    if (tid < 27) s_bone[tid] = bone[tid];

    const int t_mine = t0 + tid;
    int idx_mine = 0;
    if (t_mine < T) idx_mine = index[t_mine] & 3;
    __syncthreads();   // s_bone

    float      feetCur[12];
    float      fmin   = 0.f;
    const bool active = (t_mine < T);
    if (active) {
        fk_feet(pose + (size_t)t_mine * 216, s_bone, feetCur, fmin);
#pragma unroll
        for (int k = 0; k < 12; k++) s_feet[(tid + 1) * 12 + k] = feetCur[k];
    }
    // cross-block boundary: feet at t0-1 (redundant FK, once per block)
    if (tid == 0 && t0 > 0) {
        float fp[12]; float fd;
        fk_feet(pose + (size_t)(t0 - 1) * 216, s_bone, fp, fd);
#pragma unroll
        for (int k = 0; k < 12; k++) s_feet[k] = fp[k];
    }
    __syncthreads();

    SState v = s_identity();
    if (active) {
        float vx = 0.f, vy = GRAV, vz = 0.f;
        if (t_mine > 0) {
            vx =        s_feet[tid*12 + idx_mine*3 + 0] - feetCur[idx_mine*3 + 0];
            vy = GRAV + (s_feet[tid*12 + idx_mine*3 + 1] - feetCur[idx_mine*3 + 1]);
            vz =        s_feet[tid*12 + idx_mine*3 + 2] - feetCur[idx_mine*3 + 2];
        }
        v.sx = vx; v.sz = vz; v.a = vy; v.b = FLOOR_Y - fmin;
    }

    // block-wide inclusive scan (8 warps)
    const int lane = tid & 31, warp = tid >> 5;
#pragma unroll
    for (int d = 1; d < 32; d <<= 1) {
        float osx = __shfl_up_sync(0xFFFFFFFFu, v.sx, d);
        float osz = __shfl_up_sync(0xFFFFFFFFu, v.sz, d);
        float oa  = __shfl_up_sync(0xFFFFFFFFu, v.a,  d);
        float ob  = __shfl_up_sync(0xFFFFFFFFu, v.b,  d);
        if (lane >= d) {
            SState o; o.sx = osx; o.sz = osz; o.a = oa; o.b = ob;
            v = s_combine(o, v);
        }
    }
    if (lane == 31) s_warp[warp] = to4(v);
    __syncthreads();
    if (warp == 0) {
        SState w = s_identity();
        if (lane < THREADS / 32) w = from4(s_warp[lane]);
#pragma unroll
        for (int d = 1; d < THREADS / 32; d <<= 1) {
            float osx = __shfl_up_sync(0xFFFFFFFFu, w.sx, d);
            float osz = __shfl_up_sync(0xFFFFFFFFu, w.sz, d);
            float oa  = __shfl_up_sync(0xFFFFFFFFu, w.a,  d);
            float ob  = __shfl_up_sync(0xFFFFFFFFu, w.b,  d);
            if (lane >= d) {
                SState o; o.sx = osx; o.sz = osz; o.a = oa; o.b = ob;
                w = s_combine(o, w);
            }
        }
        if (lane < THREADS / 32) s_warp[lane] = to4(w);
    }
    __syncthreads();
    if (warp > 0) v = s_combine(from4(s_warp[warp - 1]), v);

    if (active) g_scratch[t_mine] = to4(v);
    if (tid == THREADS - 1) g_blockAgg[fkid] = to4(v);
}

// ---------------- K2: scan block aggregates (single block, 512 threads) ----------------
__global__ void __launch_bounds__(512) k2_scan(int nb)
{
    __shared__ float4 s_warp[16];
    const int tid = threadIdx.x, lane = tid & 31, warp = tid >> 5;
    SState v = s_identity();
    if (tid < nb) v = from4(g_blockAgg[tid]);
#pragma unroll
    for (int d = 1; d < 32; d <<= 1) {
        float osx = __shfl_up_sync(0xFFFFFFFFu, v.sx, d);
        float osz = __shfl_up_sync(0xFFFFFFFFu, v.sz, d);
        float oa  = __shfl_up_sync(0xFFFFFFFFu, v.a,  d);
        float ob  = __shfl_up_sync(0xFFFFFFFFu, v.b,  d);
        if (lane >= d) {
            SState o; o.sx = osx; o.sz = osz; o.a = oa; o.b = ob;
            v = s_combine(o, v);
        }
    }
    if (lane == 31) s_warp[warp] = to4(v);
    __syncthreads();
    if (warp == 0) {
        SState w = s_identity();
        if (lane < 16) w = from4(s_warp[lane]);
#pragma unroll
        for (int d = 1; d < 16; d <<= 1) {
            float osx = __shfl_up_sync(0xFFFFFFFFu, w.sx, d);
            float osz = __shfl_up_sync(0xFFFFFFFFu, w.sz, d);
            float oa  = __shfl_up_sync(0xFFFFFFFFu, w.a,  d);
            float ob  = __shfl_up_sync(0xFFFFFFFFu, w.b,  d);
            if (lane >= d) {
                SState o; o.sx = osx; o.sz = osz; o.a = oa; o.b = ob;
                w = s_combine(o, w);
            }
        }
        if (lane < 16) s_warp[lane] = to4(w);
    }
    __syncthreads();
    if (warp > 0) v = s_combine(from4(s_warp[warp - 1]), v);
    if (tid < nb) g_blockIncl[tid] = to4(v);
}

// ---------------- K3: apply block prefixes, emit trans ----------------
__global__ void __launch_bounds__(512) k3_apply(float* __restrict__ out_trans, int T)
{
    const int t = blockIdx.x * blockDim.x + threadIdx.x;
    if (t >= T) return;
    SState r = from4(g_scratch[t]);
    const int b = t / NT;
    if (b > 0) r = s_combine(from4(g_blockIncl[b - 1]), r);
    out_trans[t*3 + 0] = r.sx;
    out_trans[t*3 + 1] = fmaxf(r.a, r.b);   // root_y[t] = trans_y[t]
    out_trans[t*3 + 2] = r.sz;
}

extern "C" void kernel_launch(void* const* d_in, const int* in_sizes, int n_in,
                              void* d_out, int out_size)
{
    const float* pose  = (const float*)d_in[0];   // (T,24,3,3) f32
    const float* bone  = (const float*)d_in[1];   // (9,3) f32
    const int*   index = (const int*)d_in[2];     // (T,) i32
    float*       out   = (float*)d_out;           // [pose | trans]

    const int T     = in_sizes[2];
    const int nbFK  = (T + NT - 1) / NT;
    const int nbCopy = 2 * nbFK;
    const int grid  = 3 * nbFK;                   // interleaved: bid%3==0 -> fk

    k1_mixed<<<grid, THREADS>>>(pose, bone, index, out, T, nbFK, nbCopy);
    k2_scan<<<1, 512>>>(nbFK);
    k3_apply<<<(T + 511) / 512, 512>>>(out + (size_t)T * 216, T);
}

// round 4
// speedup vs baseline: 1.3497x; 1.1531x over previous
#include <cuda_runtime.h>
#include <math.h>
#include <stdint.h>

#define TMAX       131072
#define NT         256          // timesteps per fk block == blockDim
#define THREADS    256
#define NBF_MAX    (TMAX / NT)  // 512
#define FLOOR_Y    (-0.93f)
#define GRAV       (-0.0018f)

// ---------------- scan state: (sum_x, sum_z, a, b) ----------------
// y-recurrence: root' = max(root + vy, FLOOR_Y - fmin) == f(x)=max(x+a,b)
// composition (L earlier, R later): (La+Ra, max(Lb+Ra, Rb)); x,z plain sums.
struct SState { float sx, sz, a, b; };

__device__ __forceinline__ SState s_identity() {
    SState s; s.sx = 0.f; s.sz = 0.f; s.a = 0.f; s.b = -INFINITY; return s;
}
__device__ __forceinline__ SState s_combine(SState l, SState r) {
    SState o;
    o.sx = l.sx + r.sx;
    o.sz = l.sz + r.sz;
    o.a  = l.a  + r.a;
    o.b  = fmaxf(l.b + r.a, r.b);
    return o;
}
__device__ __forceinline__ float4 to4(SState s)   { return make_float4(s.sx, s.sz, s.a, s.b); }
__device__ __forceinline__ SState from4(float4 f) { SState s; s.sx=f.x; s.sz=f.y; s.a=f.z; s.b=f.w; return s; }

// ---------------- lookback state (static device globals) ----------------
__device__ float4 g_aggVal[NBF_MAX];
__device__ float4 g_inclVal[NBF_MAX];
__device__ int    g_flag[NBF_MAX];      // 0 = invalid, 1 = aggregate, 2 = inclusive

// ---------------- FK (vectorized loads) ----------------
__device__ __forceinline__ void mat_mul3(const float* A, const float* B, float* C) {
#pragma unroll
    for (int r = 0; r < 3; r++)
#pragma unroll
        for (int c = 0; c < 3; c++)
            C[r*3+c] = A[r*3+0]*B[0*3+c] + A[r*3+1]*B[1*3+c] + A[r*3+2]*B[2*3+c];
}
__device__ __forceinline__ void mat_vec_add3(const float* A, const float* v,
                                             const float* pin, float* pout) {
#pragma unroll
    for (int r = 0; r < 3; r++)
        pout[r] = pin[r] + A[r*3+0]*v[0] + A[r*3+1]*v[1] + A[r*3+2]*v[2];
}

// pose row = 216 floats (16B aligned). Needed float ranges: [0,27) j0,j1,j2;
// [36,54) j4,j5; [63,81) j7,j8  ->  float4 indices {0..6, 9..13, 15..20}.
// Slot offsets into M: s0=0, s1=9, s2=18, s3=36(j4), s4=45(j5), s5=63(j7), s6=72(j8).
// feet order FEET=[7,5,8,6]; fmin over p5..p8 y.
__device__ __forceinline__ void fk_feet(const float* __restrict__ row,
                                        const float* __restrict__ b,
                                        float* feet, float& fmin)
{
    const float4* __restrict__ q = (const float4*)row;
    float M[84];
#define LD4(i) *(float4*)&M[4*(i)] = q[(i)];
    LD4(0) LD4(1) LD4(2) LD4(3) LD4(4) LD4(5) LD4(6)
    LD4(9) LD4(10) LD4(11) LD4(12) LD4(13)
    LD4(15) LD4(16) LD4(17) LD4(18) LD4(19) LD4(20)
#undef LD4

    float R1[9], R2[9];
    float p0[3], pt[3];
#pragma unroll
    for (int i = 0; i < 3; i++) p0[i] = b[i];

    float p3_[3], p4_[3], p5_[3], p6_[3], p7_[3], p8_[3];

    // chain A: 0 -> 1 -> 3 -> 5 -> 7
    mat_vec_add3(M, b + 3, p0, pt);            // p1
    mat_mul3(M, M + 9, R1);                    // Rg1
    mat_vec_add3(R1, b + 9, pt, p3_);          // p3
    mat_mul3(R1, M + 36, R2);                  // Rg3
    mat_vec_add3(R2, b + 15, p3_, p5_);        // p5
    mat_mul3(R2, M + 63, R1);                  // Rg5
    mat_vec_add3(R1, b + 21, p5_, p7_);        // p7

    // chain B: 0 -> 2 -> 4 -> 6 -> 8
    mat_vec_add3(M, b + 6, p0, pt);            // p2
    mat_mul3(M, M + 18, R1);                   // Rg2
    mat_vec_add3(R1, b + 12, pt, p4_);         // p4
    mat_mul3(R1, M + 45, R2);                  // Rg4
    mat_vec_add3(R2, b + 18, p4_, p6_);        // p6
    mat_mul3(R2, M + 72, R1);                  // Rg6
    mat_vec_add3(R1, b + 24, p6_, p8_);        // p8

    feet[0] = p7_[0]; feet[1]  = p7_[1]; feet[2]  = p7_[2];
    feet[3] = p5_[0]; feet[4]  = p5_[1]; feet[5]  = p5_[2];
    feet[6] = p8_[0]; feet[7]  = p8_[1]; feet[8]  = p8_[2];
    feet[9] = p6_[0]; feet[10] = p6_[1]; feet[11] = p6_[2];
    fmin = fminf(fminf(p5_[1], p6_[1]), fminf(p7_[1], p8_[1]));
}

// ---------------- K0: reset lookback flags ----------------
__global__ void k0_reset(int nb)
{
    const int i = blockIdx.x * blockDim.x + threadIdx.x;
    if (i < nb) g_flag[i] = 0;
}

// ---------------- K1: interleaved copy blocks + fk/scan/lookback blocks ----------------
// bid % 3 == 0 -> fk block (fkid = bid/3), others -> copy block.
__global__ void __launch_bounds__(THREADS, 4)
k1_mixed(const float* __restrict__ pose, const float* __restrict__ bone,
         const int* __restrict__ index, float* __restrict__ out,
         int T, int nbFK, int nbCopy)
{
    const int tid = threadIdx.x;
    const int bid = blockIdx.x;

    if (bid % 3 != 0) {
        // ================= COPY BLOCK =================
        const int cid = bid - (bid / 3 + 1);
        const size_t tot4  = (size_t)T * 54;                 // float4 count
        const size_t chunk = (tot4 + nbCopy - 1) / nbCopy;
        const size_t beg   = (size_t)cid * chunk;
        const size_t end   = (beg + chunk < tot4) ? beg + chunk : tot4;
        if (beg >= end) return;

        const float4* __restrict__ src = (const float4*)pose;
        float4*       __restrict__ dst = (float4*)out;

        size_t pos = beg;
        while (pos + 8 * THREADS <= end) {
            float4 r0 = src[pos + 0*THREADS + tid];
            float4 r1 = src[pos + 1*THREADS + tid];
            float4 r2 = src[pos + 2*THREADS + tid];
            float4 r3 = src[pos + 3*THREADS + tid];
            float4 r4 = src[pos + 4*THREADS + tid];
            float4 r5 = src[pos + 5*THREADS + tid];
            float4 r6 = src[pos + 6*THREADS + tid];
            float4 r7 = src[pos + 7*THREADS + tid];
            __stcs(&dst[pos + 0*THREADS + tid], r0);
            __stcs(&dst[pos + 1*THREADS + tid], r1);
            __stcs(&dst[pos + 2*THREADS + tid], r2);
            __stcs(&dst[pos + 3*THREADS + tid], r3);
            __stcs(&dst[pos + 4*THREADS + tid], r4);
            __stcs(&dst[pos + 5*THREADS + tid], r5);
            __stcs(&dst[pos + 6*THREADS + tid], r6);
            __stcs(&dst[pos + 7*THREADS + tid], r7);
            pos += 8 * THREADS;
        }
        for (size_t i = pos + tid; i < end; i += THREADS)
            __stcs(&dst[i], src[i]);
        return;
    }

    // ================= FK / SCAN / LOOKBACK BLOCK =================
    const int fkid = bid / 3;
    if (fkid >= nbFK) return;

    __shared__ float  s_bone[27];
    __shared__ float  s_feet[(NT + 1) * 12];
    __shared__ float4 s_warp[THREADS / 32];
    __shared__ float4 s_aggSh, s_exclSh;

    const int t0 = fkid * NT;
    if (tid < 27) s_bone[tid] = bone[tid];

    const int t_mine = t0 + tid;
    int idx_mine = 0;
    if (t_mine < T) idx_mine = index[t_mine] & 3;
    __syncthreads();   // s_bone

    float      feetCur[12];
    float      fmin   = 0.f;
    const bool active = (t_mine < T);
    if (active) {
        fk_feet(pose + (size_t)t_mine * 216, s_bone, feetCur, fmin);
#pragma unroll
        for (int k = 0; k < 12; k++) s_feet[(tid + 1) * 12 + k] = feetCur[k];
    }
    // cross-block boundary: feet at t0-1 (extra FK on thread 0, concurrent with its own)
    if (tid == 0 && t0 > 0) {
        float fp[12]; float fd;
        fk_feet(pose + (size_t)(t0 - 1) * 216, s_bone, fp, fd);
#pragma unroll
        for (int k = 0; k < 12; k++) s_feet[k] = fp[k];
    }
    __syncthreads();

    SState v = s_identity();
    if (active) {
        float vx = 0.f, vy = GRAV, vz = 0.f;
        if (t_mine > 0) {
            vx =        s_feet[tid*12 + idx_mine*3 + 0] - feetCur[idx_mine*3 + 0];
            vy = GRAV + (s_feet[tid*12 + idx_mine*3 + 1] - feetCur[idx_mine*3 + 1]);
            vz =        s_feet[tid*12 + idx_mine*3 + 2] - feetCur[idx_mine*3 + 2];
        }
        v.sx = vx; v.sz = vz; v.a = vy; v.b = FLOOR_Y - fmin;
    }

    // ---- block-wide inclusive scan (8 warps) ----
    const int lane = tid & 31, warp = tid >> 5;
#pragma unroll
    for (int d = 1; d < 32; d <<= 1) {
        float osx = __shfl_up_sync(0xFFFFFFFFu, v.sx, d);
        float osz = __shfl_up_sync(0xFFFFFFFFu, v.sz, d);
        float oa  = __shfl_up_sync(0xFFFFFFFFu, v.a,  d);
        float ob  = __shfl_up_sync(0xFFFFFFFFu, v.b,  d);
        if (lane >= d) {
            SState o; o.sx = osx; o.sz = osz; o.a = oa; o.b = ob;
            v = s_combine(o, v);
        }
    }
    if (lane == 31) s_warp[warp] = to4(v);
    __syncthreads();
    if (warp == 0) {
        SState w = s_identity();
        if (lane < THREADS / 32) w = from4(s_warp[lane]);
#pragma unroll
        for (int d = 1; d < THREADS / 32; d <<= 1) {
            float osx = __shfl_up_sync(0xFFFFFFFFu, w.sx, d);
            float osz = __shfl_up_sync(0xFFFFFFFFu, w.sz, d);
            float oa  = __shfl_up_sync(0xFFFFFFFFu, w.a,  d);
            float ob  = __shfl_up_sync(0xFFFFFFFFu, w.b,  d);
            if (lane >= d) {
                SState o; o.sx = osx; o.sz = osz; o.a = oa; o.b = ob;
                w = s_combine(o, w);
            }
        }
        if (lane < THREADS / 32) s_warp[lane] = to4(w);
    }
    __syncthreads();
    if (warp > 0) v = s_combine(from4(s_warp[warp - 1]), v);

    // ---- publish aggregate / inclusive (thread 255 holds block aggregate) ----
    if (tid == THREADS - 1) {
        float4 a4 = to4(v);
        s_aggSh = a4;
        if (fkid == 0) {
            __stcg(&g_inclVal[0], a4);
            __threadfence();
            atomicExch(&g_flag[0], 2);
        } else {
            __stcg(&g_aggVal[fkid], a4);
            __threadfence();
            atomicExch(&g_flag[fkid], 1);
        }
    }
    if (fkid == 0 && tid == 0) s_exclSh = to4(s_identity());
    __syncthreads();

    // ---- decoupled lookback (warp 0), windowed 32 ----
    if (fkid > 0 && warp == 0) {
        SState excl = s_identity();
        int base = fkid - 1;
        for (;;) {
            const int j = base - lane;       // lane 0 = nearest predecessor
            SState val; int f;
            if (j < 0) { val = s_identity(); f = 2; }
            else {
                do {
                    f = __ldcg(&g_flag[j]);
                    if (f == 0) __nanosleep(40);
                } while (f == 0);
                __threadfence();
                float4 raw = (f == 2) ? __ldcg(&g_inclVal[j]) : __ldcg(&g_aggVal[j]);
                val = from4(raw);
            }
            const unsigned done = __ballot_sync(0xFFFFFFFFu, f == 2);
            const int L = done ? (__ffs(done) - 1) : 32;
            if (lane > L) val = s_identity();
            // ordered reduce: earlier blocks (higher lanes) on the LEFT
#pragma unroll
            for (int d = 1; d < 32; d <<= 1) {
                float osx = __shfl_down_sync(0xFFFFFFFFu, val.sx, d);
                float osz = __shfl_down_sync(0xFFFFFFFFu, val.sz, d);
                float oa  = __shfl_down_sync(0xFFFFFFFFu, val.a,  d);
                float ob  = __shfl_down_sync(0xFFFFFFFFu, val.b,  d);
                if (lane + d < 32) {
                    SState o; o.sx = osx; o.sz = osz; o.a = oa; o.b = ob;
                    val = s_combine(o, val);
                }
            }
            SState w;   // broadcast lane 0's window total
            w.sx = __shfl_sync(0xFFFFFFFFu, val.sx, 0);
            w.sz = __shfl_sync(0xFFFFFFFFu, val.sz, 0);
            w.a  = __shfl_sync(0xFFFFFFFFu, val.a,  0);
            w.b  = __shfl_sync(0xFFFFFFFFu, val.b,  0);
            excl = s_combine(w, excl);       // this window is earlier than accumulated
            if (done) break;
            base -= 32;
        }
        if (lane == 0) {
            SState incl = s_combine(excl, from4(s_aggSh));
            __stcg(&g_inclVal[fkid], to4(incl));
            __threadfence();
            atomicExch(&g_flag[fkid], 2);
            s_exclSh = to4(excl);
        }
    }
    __syncthreads();

    // ---- apply exclusive prefix, write trans directly ----
    if (active) {
        SState fin = s_combine(from4(s_exclSh), v);
        float* __restrict__ out_trans = out + (size_t)T * 216;
        out_trans[(size_t)t_mine * 3 + 0] = fin.sx;
        out_trans[(size_t)t_mine * 3 + 1] = fmaxf(fin.a, fin.b);
        out_trans[(size_t)t_mine * 3 + 2] = fin.sz;
    }
}

extern "C" void kernel_launch(void* const* d_in, const int* in_sizes, int n_in,
                              void* d_out, int out_size)
{
    const float* pose  = (const float*)d_in[0];   // (T,24,3,3) f32
    const float* bone  = (const float*)d_in[1];   // (9,3) f32
    const int*   index = (const int*)d_in[2];     // (T,) i32
    float*       out   = (float*)d_out;           // [pose | trans]

    const int T      = in_sizes[2];
    const int nbFK   = (T + NT - 1) / NT;
    const int nbCopy = 2 * nbFK;
    const int grid   = 3 * nbFK;                  // interleaved: bid%3==0 -> fk

    k0_reset<<<(nbFK + 255) / 256, 256>>>(nbFK);
    k1_mixed<<<grid, THREADS>>>(pose, bone, index, out, T, nbFK, nbCopy);
}